// round 3
// baseline (speedup 1.0000x reference)
#include <cuda_runtime.h>

#define NS   128   // states
#define NT   2048  // time steps
#define NB   64    // batch
#define NDM  128   // max duration

// Shared memory (floats):
//   ring [256*128]  mirrored exp-domain entry ring: [phys_slot][j]
//   p_sh [128]      exp(alpha - m)
//   pmat [512]      trans matvec partials  [j*4 + g]
//   pdur [512]      duration dot partials  [j*4 + (g-4)]
//   wredU[4]        per-warp max keys (warps 0..3)
#define RING_F   (256 * 128)
#define OFF_PSH  (RING_F)
#define OFF_PMAT (OFF_PSH + 128)
#define OFF_PDUR (OFF_PMAT + 512)
#define OFF_WRED (OFF_PDUR + 512)
#define SMEM_FLOATS (OFF_WRED + 4)

__device__ __forceinline__ unsigned f2key(float x) {
    int i = __float_as_int(x);
    return (unsigned)(i ^ ((i >> 31) | 0x80000000));
}
__device__ __forceinline__ float key2f(unsigned k) {
    int i = ((int)k < 0) ? (int)(k ^ 0x80000000u) : (int)(~k);
    return __int_as_float(i);
}

__global__ __launch_bounds__(1024, 1)
void hsmm_fwd_kernel(const float* __restrict__ logB,
                     const float* __restrict__ pi,
                     const float* __restrict__ A,
                     const float* __restrict__ D,
                     float* __restrict__ out)
{
    extern __shared__ float sm[];
    float*    ring  = sm;
    float*    p_sh  = sm + OFF_PSH;
    float*    pmat  = sm + OFF_PMAT;
    float*    pdur  = sm + OFF_PDUR;
    unsigned* wredU = (unsigned*)(sm + OFF_WRED);

    const int tid  = threadIdx.x;
    const int j    = tid & 127;       // state
    const int g    = tid >> 7;        // role slice 0..7 (0-3 matvec, 4-7 duration)
    const int lane = tid & 31;
    const int w    = tid >> 5;        // warp id 0..31
    const int b    = blockIdx.x;

    // Role-specialized weight table in registers (union'd across roles).
    float wtab[32];
    if (g < 4) {
        #pragma unroll
        for (int k = 0; k < 32; ++k)
            wtab[k] = __expf(A[(32 * g + k) * NS + j]);     // exp(A[i][j])
    } else {
        const int s = g - 4;
        #pragma unroll
        for (int k = 0; k < 32; ++k) {
            int dd = 32 * s + 1 + k;                        // tap index d-1 in [1,127]
            wtab[k] = (dd < NDM) ? __expf(D[j * NDM + dd]) : 0.0f;
        }
    }
    const float eD0 = __expf(D[j * NDM]);                   // d = 1 tap

    for (int idx = tid; idx < RING_F; idx += 1024) ring[idx] = 0.0f;
    __syncthreads();

    // Per-state scalars, replicated bit-identically across the 8 g-threads.
    float cum = 0.0f, cumc = 0.0f;    // Kahan cumulative emission sum
    float ref = 0.0f;                 // exp-domain reference for ring column j
    float alpha = 0.0f;
    const float* lbp = logB + (size_t)b * NT * NS + j;
    float lb_cur = lbp[0];
    const float pij = pi[j];

    for (int t = 0; t < NT; ++t) {
        float lb_next = (t + 1 < NT) ? lbp[(size_t)(t + 1) * NS] : 0.0f;
        const int slot0 = t & 127;

        if (g < 4) {
            // ---- trans matvec role (produces pmat partials) ----
            if (t > 0) {
                if (g == 0) {
                    unsigned u = f2key(alpha), r;
                    asm volatile("redux.sync.max.u32 %0, %1, 0xffffffff;" : "=r"(r) : "r"(u));
                    if (lane == 0) wredU[w] = r;
                    asm volatile("bar.sync 2, 128;" ::: "memory");
                    unsigned m0 = max(max(wredU[0], wredU[1]), max(wredU[2], wredU[3]));
                    p_sh[j] = __expf(alpha - key2f(m0));
                }
                asm volatile("bar.sync 1, 512;" ::: "memory");
                float s0 = 0.f, s1 = 0.f, s2 = 0.f, s3 = 0.f;
                const float4* pp = (const float4*)(p_sh + 32 * g);
                #pragma unroll
                for (int q = 0; q < 8; ++q) {
                    float4 pv = pp[q];
                    s0 = fmaf(pv.x, wtab[4 * q + 0], s0);
                    s1 = fmaf(pv.y, wtab[4 * q + 1], s1);
                    s2 = fmaf(pv.z, wtab[4 * q + 2], s2);
                    s3 = fmaf(pv.w, wtab[4 * q + 3], s3);
                }
                pmat[4 * j + g] = (s0 + s1) + (s2 + s3);
            }
        } else {
            // ---- duration role: dotRest over d>=2, runs barrier-free ----
            const float* rp = ring + (slot0 + 127 - 32 * (g - 4)) * NS + j;
            float d0 = 0.f, d1 = 0.f, d2 = 0.f, d3 = 0.f;
            #pragma unroll
            for (int k = 0; k < 32; k += 4) {
                d0 = fmaf(rp[-(k + 0) * NS], wtab[k + 0], d0);
                d1 = fmaf(rp[-(k + 1) * NS], wtab[k + 1], d1);
                d2 = fmaf(rp[-(k + 2) * NS], wtab[k + 2], d2);
                d3 = fmaf(rp[-(k + 3) * NS], wtab[k + 3], d3);
            }
            pdur[4 * j + (g - 4)] = (d0 + d1) + (d2 + d3);
        }
        __syncthreads();                                   // BAR C: partials ready

        // ---- combine (replicated in all 8 g-threads, bit-identical) ----
        float4 pd = *(const float4*)(pdur + 4 * j);
        float dotRest = (pd.x + pd.y) + (pd.z + pd.w);
        float m = 0.0f, S = 0.0f, v;
        if (t > 0) {
            unsigned m0 = max(max(wredU[0], wredU[1]), max(wredU[2], wredU[3]));
            m = key2f(m0);
            float4 pm = *(const float4*)(pmat + 4 * j);
            S = (pm.x + pm.y) + (pm.z + pm.w);
            v = S * __expf(m - cum - ref);                 // = exp(entry - cum - ref)
        } else {
            v = __expf(pij);                               // cum = ref = 0
        }
        const float cum_old = cum;
        float dot = dotRest + eD0 * v;

        // cum[t+1] = cum[t] + lb[t]  (Kahan)
        float y  = lb_cur - cumc;
        float tt = cum + y;
        cumc = (tt - cum) - y;
        cum  = tt;

        alpha = cum + ref + __logf(dot);

        float ins = v;
        if (v > 1e13f) {                                   // x = E - ref > 30: re-reference
            float E = ((t == 0) ? pij : m + __logf(S)) - cum_old;
            float f = __expf(ref - E);
            #pragma unroll 1
            for (int s2 = 32 * g; s2 < 32 * g + 32; ++s2)
                if ((s2 ^ slot0) & 127) ring[s2 * NS + j] *= f;
            ref = E;
            ins = 1.0f;
        } else if (dot < 1e-30f && dot > 0.0f) {           // up-rescale decayed ring
            #pragma unroll 1
            for (int s2 = 32 * g; s2 < 32 * g + 32; ++s2)
                if ((s2 ^ slot0) & 127) ring[s2 * NS + j] *= 1e30f;
            ref -= 69.0775527898f;                         // ln(1e30)
            ins *= 1e30f;
        }
        if (g == 0) {
            ring[slot0 * NS + j] = ins;                    // primary
            ring[(slot0 + 128) * NS + j] = ins;            // mirror
        }
        lb_cur = lb_next;
        __syncthreads();                                   // BAR X: loop carry
    }

    // loglik[b] = LSE_j alpha[T-1, j]  (g==0 warps hold all 128 states)
    if (g == 0) {
        float vv = alpha;
        #pragma unroll
        for (int o = 16; o > 0; o >>= 1)
            vv = fmaxf(vv, __shfl_xor_sync(0xffffffffu, vv, o));
        if (lane == 0) pdur[w] = vv;
    }
    __syncthreads();
    float m = fmaxf(fmaxf(pdur[0], pdur[1]), fmaxf(pdur[2], pdur[3]));
    if (g == 0) {
        float e = __expf(alpha - m);
        #pragma unroll
        for (int o = 16; o > 0; o >>= 1)
            e += __shfl_xor_sync(0xffffffffu, e, o);
        if (lane == 0) pdur[8 + w] = e;
    }
    __syncthreads();
    if (tid == 0) {
        float ssum = (pdur[8] + pdur[9]) + (pdur[10] + pdur[11]);
        out[b] = m + __logf(ssum);
    }
}

extern "C" void kernel_launch(void* const* d_in, const int* in_sizes, int n_in,
                              void* d_out, int out_size)
{
    const float* logB = (const float*)d_in[0];
    const float* pi   = (const float*)d_in[1];
    const float* A    = (const float*)d_in[2];
    const float* D    = (const float*)d_in[3];
    float* out = (float*)d_out;

    const size_t smem_bytes = (size_t)SMEM_FLOATS * sizeof(float);  // ~132.6 KB
    cudaFuncSetAttribute(hsmm_fwd_kernel,
                         cudaFuncAttributeMaxDynamicSharedMemorySize,
                         (int)smem_bytes);
    hsmm_fwd_kernel<<<NB, 1024, smem_bytes>>>(logB, pi, A, D, out);
}

// round 4
// speedup vs baseline: 2.9603x; 2.9603x over previous
#include <cuda_runtime.h>

#define NS   128   // states
#define NT   2048  // time steps
#define NB   64    // batch
#define NDM  128   // max duration

// Shared memory (floats):
//   ring  [256*128] mirrored exp-domain entry ring: [phys_slot][j]
//   p_sh  [128]     exp(alpha - m_warp) (per-chunk scaled)
//   pmat  [512]     trans matvec partials [4*j + g]
//   pdur  [2][512]  duration tail partials, double-buffered by step parity
//   wred  [4]       per-warp alpha maxes (float)
//   flag  [2][128]  per-column rescale factor for next step (1.0 = none)
#define RING_F   (256 * 128)
#define OFF_PSH  (RING_F)
#define OFF_PMAT (OFF_PSH + 128)
#define OFF_PDUR (OFF_PMAT + 512)
#define OFF_WRED (OFF_PDUR + 1024)
#define OFF_FLAG (OFF_WRED + 4)
#define SMEM_FLOATS (OFF_FLAG + 256)

__global__ __launch_bounds__(1024, 1)
void hsmm_fwd_kernel(const float* __restrict__ logB,
                     const float* __restrict__ pi,
                     const float* __restrict__ A,
                     const float* __restrict__ D,
                     float* __restrict__ out)
{
    extern __shared__ float sm[];
    float* ring = sm;
    float* p_sh = sm + OFF_PSH;
    float* pmat = sm + OFF_PMAT;
    float* pdur = sm + OFF_PDUR;
    float* wred = sm + OFF_WRED;
    float* flag = sm + OFF_FLAG;

    const int tid  = threadIdx.x;
    const int j    = tid & 127;        // state
    const int g    = tid >> 7;         // role slice: 0-3 matvec(+combine), 4-7 duration tail
    const int lane = tid & 31;
    const int w    = tid >> 5;
    const int b    = blockIdx.x;

    // Role-specialized register tables.
    float wtab[32];
    if (g < 4) {
        #pragma unroll
        for (int k = 0; k < 32; ++k)
            wtab[k] = __expf(A[(32 * g + k) * NS + j]);        // exp(A[i][j])
    } else {
        const int s = g - 4;
        #pragma unroll
        for (int k = 0; k < 32; ++k) {
            int idx = 2 + 32 * s + k;                          // tap d-1 in [2,127]
            wtab[k] = (idx < NDM) ? __expf(D[j * NDM + idx]) : 0.0f;
        }
    }

    // smem init
    for (int idx = tid; idx < RING_F; idx += 1024) ring[idx] = 0.0f;
    pdur[tid & 1023] = 0.0f;                                   // both pdur buffers (1024 floats)
    if (tid < 256) flag[tid] = 1.0f;
    if (tid < 4)   wred[tid] = 0.0f;

    // g==0 per-state scalars (live only in warps 0-3)
    float alpha = 0.0f, cum = 0.0f, ref = 0.0f;
    float v_prev = 0.0f, fpend = 1.0f;
    float pij = 0.0f, eD0 = 0.0f, eD1 = 0.0f, lb_cur = 0.0f;
    const float* lbp = logB + (size_t)b * NT * NS + j;
    if (g == 0) {
        pij = pi[j];
        eD0 = __expf(D[j * NDM + 0]);
        eD1 = __expf(D[j * NDM + 1]);
        lb_cur = lbp[0];
    }
    __syncthreads();

    for (int t = 0; t < NT; ++t) {
        if (g >= 4) {
            // ---- duration tail role: pdur for step t+1, taps d>=3, slots <= t-1 ----
            const int s = g - 4;
            const int base = ((t - 1) & 127) + 128 - 32 * s;   // phys slot of tap offset 32s
            float fac = flag[(t & 1) * 128 + j];
            if (fac != 1.0f) {
                // Rescale my read window + mirror partners (disjoint across s; no barrier).
                #pragma unroll 1
                for (int kk = 0; kk < 32; ++kk) {
                    int off = 32 * s + kk;
                    if (off == 0 || off > 125) continue;       // off0: already new units; >125: dead
                    int p = base - kk;
                    float val = ring[p * NS + j] * fac;
                    ring[p * NS + j] = val;
                    int q = (p >= 128) ? (p - 128) : (p + 128);
                    ring[q * NS + j] = val;
                }
            }
            const float* rp = ring + base * NS + j;
            float d0 = 0.f, d1 = 0.f, d2 = 0.f, d3 = 0.f;
            #pragma unroll
            for (int k = 0; k < 32; k += 4) {
                d0 = fmaf(rp[-(k + 0) * NS], wtab[k + 0], d0);
                d1 = fmaf(rp[-(k + 1) * NS], wtab[k + 1], d1);
                d2 = fmaf(rp[-(k + 2) * NS], wtab[k + 2], d2);
                d3 = fmaf(rp[-(k + 3) * NS], wtab[k + 3], d3);
            }
            pdur[((t + 1) & 1) * 512 + 4 * j + s] = (d0 + d1) + (d2 + d3);
        } else {
            // ---- trans matvec role ----
            if (t > 0) {
                float s0 = 0.f, s1 = 0.f, s2 = 0.f, s3 = 0.f;
                const float4* pp = (const float4*)(p_sh + 32 * g);
                #pragma unroll
                for (int q = 0; q < 8; ++q) {
                    float4 pv = pp[q];
                    s0 = fmaf(pv.x, wtab[4 * q + 0], s0);
                    s1 = fmaf(pv.y, wtab[4 * q + 1], s1);
                    s2 = fmaf(pv.z, wtab[4 * q + 2], s2);
                    s3 = fmaf(pv.w, wtab[4 * q + 3], s3);
                }
                pmat[4 * j + g] = (s0 + s1) + (s2 + s3);
            }
            asm volatile("bar.sync 3, 512;" ::: "memory");     // pmat ready

            if (g == 0) {
                // ---- combine: one thread per state ----
                float v;
                if (t == 0) {
                    v = __expf(pij);                           // cum = ref = 0
                } else {
                    float a0 = cum + ref;
                    float4 pm = *(const float4*)(pmat + 4 * j);
                    float K0 = __expf(wred[0] - a0);
                    float K1 = __expf(wred[1] - a0);
                    float K2 = __expf(wred[2] - a0);
                    float K3 = __expf(wred[3] - a0);
                    v = fmaf(pm.x, K0, fmaf(pm.y, K1, fmaf(pm.z, K2, pm.w * K3)));
                }
                float4 pd = *(const float4*)(pdur + (t & 1) * 512 + 4 * j);
                float tail = (pd.x + pd.y) + (pd.z + pd.w);
                float dot = fmaf(fpend, tail, fmaf(eD1, v_prev, eD0 * v));

                cum += lb_cur;                                 // cum[t+1]
                alpha = cum + ref + __logf(dot);
                lb_cur = (t + 1 < NT) ? lbp[(size_t)(t + 1) * NS] : 0.0f;  // prefetch

                // Re-reference: scheduled every 16 steps, reactive on overflow risk.
                float ins, fac;
                bool resc = (v > 1e13f) | (((t & 15) == 15) & (v > 1e-35f));
                if (resc) {
                    float lv = __logf(v);
                    ref += lv;
                    ins = 1.0f;
                    fac = __expf(-lv);
                } else {
                    ins = v;
                    fac = 1.0f;
                }
                fpend = fac;
                flag[((t + 1) & 1) * 128 + j] = fac;
                const int sl0 = t & 127;
                ring[sl0 * NS + j] = ins;                      // primary
                ring[(sl0 + 128) * NS + j] = ins;              // mirror
                v_prev = ins;

                // warp-local max + p_sh for next step's matvec
                float mv = alpha;
                #pragma unroll
                for (int o = 16; o > 0; o >>= 1)
                    mv = fmaxf(mv, __shfl_xor_sync(0xffffffffu, mv, o));
                if (lane == 0) wred[w] = mv;
                p_sh[j] = __expf(alpha - mv);
            }
        }
        __syncthreads();                                       // loop carry: publishes everything
    }

    // loglik[b] = LSE_j alpha[T-1, j]  (alpha lives in g==0, warps 0-3)
    if (g == 0) {
        float mv = alpha;
        #pragma unroll
        for (int o = 16; o > 0; o >>= 1)
            mv = fmaxf(mv, __shfl_xor_sync(0xffffffffu, mv, o));
        if (lane == 0) pmat[w] = mv;
    }
    __syncthreads();
    float m = fmaxf(fmaxf(pmat[0], pmat[1]), fmaxf(pmat[2], pmat[3]));
    if (g == 0) {
        float e = __expf(alpha - m);
        #pragma unroll
        for (int o = 16; o > 0; o >>= 1)
            e += __shfl_xor_sync(0xffffffffu, e, o);
        if (lane == 0) pmat[8 + w] = e;
    }
    __syncthreads();
    if (tid == 0) {
        float ssum = (pmat[8] + pmat[9]) + (pmat[10] + pmat[11]);
        out[b] = m + __logf(ssum);
    }
}

extern "C" void kernel_launch(void* const* d_in, const int* in_sizes, int n_in,
                              void* d_out, int out_size)
{
    const float* logB = (const float*)d_in[0];
    const float* pi   = (const float*)d_in[1];
    const float* A    = (const float*)d_in[2];
    const float* D    = (const float*)d_in[3];
    float* out = (float*)d_out;

    const size_t smem_bytes = (size_t)SMEM_FLOATS * sizeof(float);  // ~134.6 KB
    cudaFuncSetAttribute(hsmm_fwd_kernel,
                         cudaFuncAttributeMaxDynamicSharedMemorySize,
                         (int)smem_bytes);
    hsmm_fwd_kernel<<<NB, 1024, smem_bytes>>>(logB, pi, A, D, out);
}